// round 10
// baseline (speedup 1.0000x reference)
#include <cuda_runtime.h>
#include <cstdint>

#define BB 32
#define TT 512
#define II 128
#define HH 1024
#define GG 4096
#define OO 128
#define BD 64              // duplicated batch dimension (2*BB)

#define NTH 256
#define NBLK 276
#define STG 768            // floats per stage (w 8x32 + hdup 8x64)
#define WREG 2304          // floats per warp smem region (3 stages x 768)
#define RPAD 18            // u64 per reduction row: 16 data + 2 pad
#define SMEM_BYTES 73728   // 8 warps * 2304 floats * 4B

// ---------------- device scratch ----------------
__device__ float Wp_ih0[II * GG];   // [k][n], n = j*4+g
__device__ float Wp_hh0[HH * GG];
__device__ float Wp_ih1[HH * GG];
__device__ float Wp_hh1[HH * GG];
__device__ float Wp_out[HH * OO];   // [k][o]
__device__ float gb0[GG];
__device__ float gb1[GG];
__device__ float xTg[TT * II * BD]; // x transposed + pair-duplicated: [t][k][2b]
__device__ float h0s[2][HH][BD];    // layer0 hidden, transposed + dup [j][2b], double-buffered
__device__ float h2s[2][HH][BD];    // layer1 hidden
__device__ unsigned g_cnt;
__device__ unsigned g_flag;

// ---------------- prep: reset states/barrier + permute weights + transpose/dup x ----------------
__global__ void prep_kernel(const float* __restrict__ xin,
                            const float* __restrict__ Wih0, const float* __restrict__ Whh0,
                            const float* __restrict__ b0v, const float* __restrict__ Wih1,
                            const float* __restrict__ Whh1, const float* __restrict__ b1v,
                            const float* __restrict__ Wout) {
    int idx0 = blockIdx.x * blockDim.x + threadIdx.x;
    int stride = gridDim.x * blockDim.x;
    if (idx0 == 0) { g_cnt = 0u; g_flag = 0u; }
    float* hz0 = &h0s[0][0][0];
    float* hz1 = &h2s[0][0][0];
    for (int i = idx0; i < 2 * HH * BD; i += stride) { hz0[i] = 0.f; hz1[i] = 0.f; }

    // xT[t][k][2b] = xT[t][k][2b+1] = x[b][t][k]
    for (int i = idx0; i < TT * II * BD; i += stride) {
        int b = (i & (BD - 1)) >> 1;
        int k = (i >> 6) & (II - 1);
        int t = i >> 13;
        xTg[i] = xin[((size_t)b * TT + t) * II + k];
    }

    const int S0 = II * GG;
    const int S1 = HH * GG;
    const int S4 = HH * OO;
    const int total = S0 + 3 * S1 + S4 + 2 * GG;
    for (int idx = idx0; idx < total; idx += stride) {
        int r = idx;
        if (r < S0) {
            int k = r >> 12, n = r & (GG - 1);
            int g = n & 3, j = n >> 2;
            Wp_ih0[r] = Wih0[(g * HH + j) * II + k];
        } else if ((r -= S0) < S1) {
            int k = r >> 12, n = r & (GG - 1);
            int g = n & 3, j = n >> 2;
            Wp_hh0[r] = Whh0[(g * HH + j) * HH + k];
        } else if ((r -= S1) < S1) {
            int k = r >> 12, n = r & (GG - 1);
            int g = n & 3, j = n >> 2;
            Wp_ih1[r] = Wih1[(g * HH + j) * HH + k];
        } else if ((r -= S1) < S1) {
            int k = r >> 12, n = r & (GG - 1);
            int g = n & 3, j = n >> 2;
            Wp_hh1[r] = Whh1[(g * HH + j) * HH + k];
        } else if ((r -= S1) < S4) {
            Wp_out[r] = Wout[(r & (OO - 1)) * HH + (r >> 7)];
        } else if ((r -= S4) < GG) {
            gb0[r] = b0v[(r & 3) * HH + (r >> 2)];
        } else {
            r -= GG;
            gb1[r] = b1v[(r & 3) * HH + (r >> 2)];
        }
    }
}

// ---------------- packed fp32x2 ops + cp.async ----------------
#define FMA2(acc, a, b) asm("fma.rn.f32x2 %0, %1, %2, %0;" : "+l"(acc) : "l"(a), "l"(b))
#define ADD2(acc, a)    asm("add.rn.f32x2 %0, %0, %1;" : "+l"(acc) : "l"(a))

__device__ __forceinline__ void cpa16(uint32_t dst, const float* src) {
    asm volatile("cp.async.cg.shared.global [%0], [%1], 16;" :: "r"(dst), "l"(src));
}
#define CP_COMMIT() asm volatile("cp.async.commit_group;")

__device__ __forceinline__ float sigf(float x) { return 1.0f / (1.0f + __expf(-x)); }
__device__ __forceinline__ float tanhfast(float x) {
    return 1.0f - __fdividef(2.0f, __expf(2.0f * x) + 1.0f);
}
__device__ __forceinline__ float2 u2f(unsigned long long v) {
    float2 f;
    f.x = __uint_as_float((unsigned)v);
    f.y = __uint_as_float((unsigned)(v >> 32));
    return f;
}

// ---------------- grid barrier (sense/epoch) ----------------
__device__ __forceinline__ void grid_bar(int p) {
    if (threadIdx.x < 32) __threadfence();   // global writers are warp 0
    __syncthreads();
    if (threadIdx.x == 0) {
        unsigned tgt = (unsigned)(p + 1);
        unsigned old = atomicAdd(&g_cnt, 1u);
        if (old == tgt * NBLK - 1u) {
            asm volatile("st.global.release.gpu.u32 [%0], %1;" :: "l"(&g_flag), "r"(tgt) : "memory");
        } else {
            unsigned v;
            do {
                asm volatile("ld.global.acquire.gpu.u32 %0, [%1];" : "=r"(v) : "l"(&g_flag) : "memory");
                if (v >= tgt) break;
                __nanosleep(128);
            } while (true);
        }
    }
    __syncthreads();
}

// Block: 8 warps = 8 contiguous k-splits. Thread: 8 cols x 4 batches.
// Warp smem region: ring of 3 stages x (w 8x32 | hdup 8x64) = 768 floats.

// ROLE 0 = layer0 (K=1152: 128 x + 1024 h), ROLE 1 = layer1 (K=2048), ROLE 2 = head (K=1024)
template <int ROLE>
__device__ __forceinline__ void produce(int s, int buf, int t, int cg, int base_k,
                                        uint32_t warp_sm,
                                        const float* __restrict__ hA,
                                        const float* __restrict__ hB) {
    const int lane = threadIdx.x & 31;
    const int kg = base_k + s * 8;
    const float* wsrc;
    const float* hsrc;
    constexpr int WS = (ROLE == 2) ? OO : GG;
    if (ROLE == 0) {
        if (kg < II) { wsrc = Wp_ih0 + (size_t)kg * GG; hsrc = xTg + ((size_t)t * II + kg) * BD; }
        else         { wsrc = Wp_hh0 + (size_t)(kg - II) * GG; hsrc = hA + (size_t)(kg - II) * BD; }
    } else if (ROLE == 1) {
        if (kg < HH) { wsrc = Wp_ih1 + (size_t)kg * GG; hsrc = hA + (size_t)kg * BD; }
        else         { wsrc = Wp_hh1 + (size_t)(kg - HH) * GG; hsrc = hB + (size_t)(kg - HH) * BD; }
    } else {
        wsrc = Wp_out + (size_t)kg * OO; hsrc = hB + (size_t)kg * BD;
    }
    wsrc += cg * 32;

    const uint32_t wd = warp_sm + (unsigned)(buf * STG) * 4u;
    const uint32_t hd = wd + 1024u;   // 256 floats
    // w: 8 rows x 32 floats, 2 chunks/lane
#pragma unroll
    for (int i = 0; i < 2; ++i) {
        int u = lane + i * 32;
        int row = u >> 3, part = u & 7;
        cpa16(wd + (unsigned)(row * 32 + part * 4) * 4u, wsrc + (size_t)row * WS + part * 4);
    }
    // hdup: 8 rows x 64 floats, 4 chunks/lane
#pragma unroll
    for (int i = 0; i < 4; ++i) {
        int u = lane + i * 32;
        int row = u >> 4, part = u & 15;
        cpa16(hd + (unsigned)(row * 64 + part * 4) * 4u, hsrc + (size_t)row * BD + part * 4);
    }
}

template <int ROLE, int NS>
__device__ __forceinline__ void do_pass(int p, int t, int cg, float* smemf, uint32_t smem_b,
                                        const float* __restrict__ b_out,
                                        float* __restrict__ out,
                                        float* creg) {
    const int tid = threadIdx.x;
    const int ks = tid >> 5;          // warp = contiguous k-split (8)
    const int lane = tid & 31;
    const int bg = lane >> 2;         // 8 batch groups of 4
    const int ng = lane & 3;          // 4 col groups of 8
    const int n0 = cg * 32 + ng * 8;
    const int b0 = bg * 4;
    const int par = p & 1, prev = par ^ 1;
    const int base_k = ks * NS * 8;

    const float* __restrict__ hA = &h0s[prev][0][0];
    const float* __restrict__ hB = &h2s[prev][0][0];

    const uint32_t warp_sm = smem_b + (unsigned)(ks * WREG) * 4u;
    const float* warp_f = smemf + ks * WREG;

    unsigned long long acc[4][4];
#pragma unroll
    for (int i = 0; i < 4; ++i)
#pragma unroll
        for (int j = 0; j < 4; ++j) acc[i][j] = 0ull;

    // prologue: 2 stages in flight (3-buffer ring)
    produce<ROLE>(0, 0, t, cg, base_k, warp_sm, hA, hB); CP_COMMIT();
    produce<ROLE>(1, 1, t, cg, base_k, warp_sm, hA, hB); CP_COMMIT();

    int bc = 0;   // consume buffer
    int bp = 2;   // produce buffer
    for (int s = 0; s < NS; ++s) {
        if (s + 2 < NS) {
            produce<ROLE>(s + 2, bp, t, cg, base_k, warp_sm, hA, hB);
            CP_COMMIT();
            asm volatile("cp.async.wait_group 2;");
            bp = (bp == 2) ? 0 : bp + 1;
        } else {
            if (s + 1 < NS) asm volatile("cp.async.wait_group 1;");
            else            asm volatile("cp.async.wait_group 0;");
        }
        __syncwarp();

        const float* wp = warp_f + bc * STG + ng * 8;
        const float* hp = warp_f + bc * STG + 256 + bg * 8;
        bc = (bc == 2) ? 0 : bc + 1;
#pragma unroll
        for (int r = 0; r < 8; ++r) {
            ulonglong2 w0 = *reinterpret_cast<const ulonglong2*>(wp);
            ulonglong2 w1 = *reinterpret_cast<const ulonglong2*>(wp + 4);
            ulonglong2 h01 = *reinterpret_cast<const ulonglong2*>(hp);      // (b0,b0),(b1,b1)
            ulonglong2 h23 = *reinterpret_cast<const ulonglong2*>(hp + 4);  // (b2,b2),(b3,b3)
            FMA2(acc[0][0], w0.x, h01.x); FMA2(acc[0][1], w0.x, h01.y);
            FMA2(acc[0][2], w0.x, h23.x); FMA2(acc[0][3], w0.x, h23.y);
            FMA2(acc[1][0], w0.y, h01.x); FMA2(acc[1][1], w0.y, h01.y);
            FMA2(acc[1][2], w0.y, h23.x); FMA2(acc[1][3], w0.y, h23.y);
            FMA2(acc[2][0], w1.x, h01.x); FMA2(acc[2][1], w1.x, h01.y);
            FMA2(acc[2][2], w1.x, h23.x); FMA2(acc[2][3], w1.x, h23.y);
            FMA2(acc[3][0], w1.y, h01.x); FMA2(acc[3][1], w1.y, h01.y);
            FMA2(acc[3][2], w1.y, h23.x); FMA2(acc[3][3], w1.y, h23.y);
            wp += 32;
            hp += 64;
        }
    }

    // ---- k-split reduction through smem (overlay; stage ring fully drained) ----
    __syncthreads();
    unsigned long long* red = reinterpret_cast<unsigned long long*>(smemf);
    unsigned long long* myrow = red + (size_t)tid * RPAD;
#pragma unroll
    for (int q = 0; q < 4; ++q) {
        ulonglong2 v0, v1;
        v0.x = acc[q][0]; v0.y = acc[q][1];
        v1.x = acc[q][2]; v1.y = acc[q][3];
        *reinterpret_cast<ulonglong2*>(myrow + q * 4) = v0;
        *reinterpret_cast<ulonglong2*>(myrow + q * 4 + 2) = v1;
    }
    __syncthreads();
    if (ks == 0) {
        unsigned long long s[16];
#pragma unroll
        for (int q = 0; q < 16; ++q) s[q] = 0ull;
#pragma unroll
        for (int w = 0; w < 8; ++w) {
            unsigned long long* rp = red + (size_t)(w * 32 + lane) * RPAD;
#pragma unroll
            for (int m = 0; m < 8; ++m) {
                ulonglong2 v = *reinterpret_cast<ulonglong2*>(rp + m * 2);
                ADD2(s[m * 2], v.x);
                ADD2(s[m * 2 + 1], v.y);
            }
        }
        // s[4q+bi]: col-pair q of {(i,f)j0,(g,o)j0,(i,f)j1,(g,o)j1}, batch b0+bi

        if (ROLE < 2) {
            const float* gbv = (ROLE == 0) ? gb0 : gb1;
            float* hdst = (ROLE == 0) ? &h0s[par][0][0] : &h2s[par][0][0];
            const int j0 = n0 >> 2;
#pragma unroll
            for (int jj = 0; jj < 2; ++jj) {
                float bi_ = gbv[n0 + jj * 4 + 0];
                float bf_ = gbv[n0 + jj * 4 + 1];
                float bg_ = gbv[n0 + jj * 4 + 2];
                float bo_ = gbv[n0 + jj * 4 + 3];
                float hv[4];
#pragma unroll
                for (int bi = 0; bi < 4; ++bi) {
                    float2 gif = u2f(s[(2 * jj) * 4 + bi]);      // (i, f)
                    float2 ggo = u2f(s[(2 * jj + 1) * 4 + bi]);  // (g, o)
                    float ig = sigf(gif.x + bi_);
                    float fg = sigf(gif.y + bf_);
                    float gt = tanhfast(ggo.x + bg_);
                    float og = sigf(ggo.y + bo_);
                    float cn = fg * creg[jj * 4 + bi] + ig * gt;
                    creg[jj * 4 + bi] = cn;
                    hv[bi] = og * tanhfast(cn);
                }
                // duplicated store: [j][2b]
                float* hr = &hdst[(size_t)(j0 + jj) * BD + b0 * 2];
                __stcg(reinterpret_cast<float4*>(hr),     make_float4(hv[0], hv[0], hv[1], hv[1]));
                __stcg(reinterpret_cast<float4*>(hr + 4), make_float4(hv[2], hv[2], hv[3], hv[3]));
            }
        } else {
            float bo[8];
#pragma unroll
            for (int q = 0; q < 8; ++q) bo[q] = b_out[n0 + q];
#pragma unroll
            for (int bi = 0; bi < 4; ++bi) {
                float2 p0 = u2f(s[0 * 4 + bi]);
                float2 p1 = u2f(s[1 * 4 + bi]);
                float2 p2 = u2f(s[2 * 4 + bi]);
                float2 p3 = u2f(s[3 * 4 + bi]);
                float4 lo = make_float4(p0.x + bo[0], p0.y + bo[1], p1.x + bo[2], p1.y + bo[3]);
                float4 hi = make_float4(p2.x + bo[4], p2.y + bo[5], p3.x + bo[6], p3.y + bo[7]);
                float* op = out + ((size_t)(b0 + bi) * TT + t) * OO + n0;
                *reinterpret_cast<float4*>(op) = lo;
                *reinterpret_cast<float4*>(op + 4) = hi;
            }
        }
    }
}

// ---------------- persistent pipelined kernel ----------------
extern __shared__ float smemf[];

__global__ void __launch_bounds__(NTH, 2) lstm_kernel(const float* __restrict__ b_out,
                                                      float* __restrict__ out) {
    const int bid = blockIdx.x;
    const uint32_t smem_b = (uint32_t)__cvta_generic_to_shared(smemf);
    float creg[8];
#pragma unroll
    for (int i = 0; i < 8; ++i) creg[i] = 0.f;

    if (bid < 128) {
        // layer 0: t = p; K=1152, 18 stages/warp
        for (int p = 0; p < TT + 2; ++p) {
            if (p < TT) do_pass<0, 18>(p, p, bid, smemf, smem_b, b_out, out, creg);
            grid_bar(p);
        }
    } else if (bid < 132) {
        // head: t = p - 2; K=1024, 16 stages/warp
        for (int p = 0; p < TT + 2; ++p) {
            if (p >= 2) do_pass<2, 16>(p, p - 2, bid - 128, smemf, smem_b, b_out, out, creg);
            grid_bar(p);
        }
    } else if (bid < 148) {
        // idle (keeps barrier count uniform)
        for (int p = 0; p < TT + 2; ++p) grid_bar(p);
    } else {
        // layer 1: t = p - 1; K=2048, 32 stages/warp (pairs with layer-0 block bid-148 on same SM)
        for (int p = 0; p < TT + 2; ++p) {
            if (p >= 1 && p <= TT) do_pass<1, 32>(p, p - 1, bid - 148, smemf, smem_b, b_out, out, creg);
            grid_bar(p);
        }
    }
}

// ---------------- launch ----------------
extern "C" void kernel_launch(void* const* d_in, const int* in_sizes, int n_in,
                              void* d_out, int out_size) {
    const float* x     = (const float*)d_in[0];
    const float* Wih0  = (const float*)d_in[1];
    const float* Whh0  = (const float*)d_in[2];
    const float* b0v   = (const float*)d_in[3];
    const float* Wih1  = (const float*)d_in[4];
    const float* Whh1  = (const float*)d_in[5];
    const float* b1v   = (const float*)d_in[6];
    const float* Wout  = (const float*)d_in[7];
    const float* boutv = (const float*)d_in[8];
    float* out = (float*)d_out;

    static bool attr_set = false;
    if (!attr_set) {
        cudaFuncSetAttribute(lstm_kernel, cudaFuncAttributeMaxDynamicSharedMemorySize, SMEM_BYTES);
        attr_set = true;
    }

    prep_kernel<<<512, 256>>>(x, Wih0, Whh0, b0v, Wih1, Whh1, b1v, Wout);
    lstm_kernel<<<NBLK, NTH, SMEM_BYTES>>>(boutv, out);
}

// round 11
// speedup vs baseline: 1.0242x; 1.0242x over previous
#include <cuda_runtime.h>
#include <cstdint>

#define BB 32
#define TT 512
#define II 128
#define HH 1024
#define GG 4096
#define OO 128

#define NTH 256
#define NBLK 520
#define STG 384            // floats per stage: w 8x16 (128) + h 8x32 (256)
#define WREG 1536          // floats per warp smem region (4 stages x 384)
#define RPAD 9             // u64 per reduction row: 8 data + 1 pad
#define SMEM_BYTES 49152   // 8 warps * 1536 floats * 4B

// ---------------- device scratch ----------------
__device__ float Wp_ih0[II * GG];   // [k][n], n = j*4+g
__device__ float Wp_hh0[HH * GG];
__device__ float Wp_ih1[HH * GG];
__device__ float Wp_hh1[HH * GG];
__device__ float Wp_out[HH * OO];   // [k][o]
__device__ float gb0[GG];
__device__ float gb1[GG];
__device__ float xTg[TT * II * BB]; // x transposed: [t][k][b]
__device__ float h0s[2][HH][BB];    // layer0 hidden, transposed [j][b], double-buffered
__device__ float h2s[2][HH][BB];    // layer1 hidden
__device__ unsigned g_cnt;
__device__ unsigned g_flag;

// ---------------- prep: reset states/barrier + permute weights + transpose x ----------------
__global__ void prep_kernel(const float* __restrict__ xin,
                            const float* __restrict__ Wih0, const float* __restrict__ Whh0,
                            const float* __restrict__ b0v, const float* __restrict__ Wih1,
                            const float* __restrict__ Whh1, const float* __restrict__ b1v,
                            const float* __restrict__ Wout) {
    int idx0 = blockIdx.x * blockDim.x + threadIdx.x;
    int stride = gridDim.x * blockDim.x;
    if (idx0 == 0) { g_cnt = 0u; g_flag = 0u; }
    float* hz0 = &h0s[0][0][0];
    float* hz1 = &h2s[0][0][0];
    for (int i = idx0; i < 2 * HH * BB; i += stride) { hz0[i] = 0.f; hz1[i] = 0.f; }

    // transpose x: xT[t][k][b] = x[b][t][k]
    for (int i = idx0; i < TT * II * BB; i += stride) {
        int b = i & (BB - 1);
        int k = (i >> 5) & (II - 1);
        int t = i >> 12;
        xTg[i] = xin[((size_t)b * TT + t) * II + k];
    }

    const int S0 = II * GG;
    const int S1 = HH * GG;
    const int S4 = HH * OO;
    const int total = S0 + 3 * S1 + S4 + 2 * GG;
    for (int idx = idx0; idx < total; idx += stride) {
        int r = idx;
        if (r < S0) {
            int k = r >> 12, n = r & (GG - 1);
            int g = n & 3, j = n >> 2;
            Wp_ih0[r] = Wih0[(g * HH + j) * II + k];
        } else if ((r -= S0) < S1) {
            int k = r >> 12, n = r & (GG - 1);
            int g = n & 3, j = n >> 2;
            Wp_hh0[r] = Whh0[(g * HH + j) * HH + k];
        } else if ((r -= S1) < S1) {
            int k = r >> 12, n = r & (GG - 1);
            int g = n & 3, j = n >> 2;
            Wp_ih1[r] = Wih1[(g * HH + j) * HH + k];
        } else if ((r -= S1) < S1) {
            int k = r >> 12, n = r & (GG - 1);
            int g = n & 3, j = n >> 2;
            Wp_hh1[r] = Whh1[(g * HH + j) * HH + k];
        } else if ((r -= S1) < S4) {
            Wp_out[r] = Wout[(r & (OO - 1)) * HH + (r >> 7)];
        } else if ((r -= S4) < GG) {
            gb0[r] = b0v[(r & 3) * HH + (r >> 2)];
        } else {
            r -= GG;
            gb1[r] = b1v[(r & 3) * HH + (r >> 2)];
        }
    }
}

// ---------------- packed fp32x2 ops + cp.async ----------------
#define FMA2(acc, a, b) asm("fma.rn.f32x2 %0, %1, %2, %0;" : "+l"(acc) : "l"(a), "l"(b))
#define ADD2(acc, a)    asm("add.rn.f32x2 %0, %0, %1;" : "+l"(acc) : "l"(a))
#define PACK2(d, v)     asm("mov.b64 %0, {%1, %1};" : "=l"(d) : "r"(v))

__device__ __forceinline__ void cpa16(uint32_t dst, const float* src) {
    asm volatile("cp.async.cg.shared.global [%0], [%1], 16;" :: "r"(dst), "l"(src));
}
#define CP_COMMIT() asm volatile("cp.async.commit_group;")

__device__ __forceinline__ float sigf(float x) { return 1.0f / (1.0f + __expf(-x)); }
__device__ __forceinline__ float tanhfast(float x) {
    return 1.0f - __fdividef(2.0f, __expf(2.0f * x) + 1.0f);
}
__device__ __forceinline__ float2 u2f(unsigned long long v) {
    float2 f;
    f.x = __uint_as_float((unsigned)v);
    f.y = __uint_as_float((unsigned)(v >> 32));
    return f;
}

// ---------------- grid barrier (sense/epoch) ----------------
__device__ __forceinline__ void grid_bar(int p) {
    if (threadIdx.x < 32) __threadfence();   // global writers are warp 0
    __syncthreads();
    if (threadIdx.x == 0) {
        unsigned tgt = (unsigned)(p + 1);
        unsigned old = atomicAdd(&g_cnt, 1u);
        if (old == tgt * NBLK - 1u) {
            asm volatile("st.global.release.gpu.u32 [%0], %1;" :: "l"(&g_flag), "r"(tgt) : "memory");
        } else {
            unsigned v;
            do {
                asm volatile("ld.global.acquire.gpu.u32 %0, [%1];" : "=r"(v) : "l"(&g_flag) : "memory");
                if (v >= tgt) break;
                __nanosleep(128);
            } while (true);
        }
    }
    __syncthreads();
}

// Block: 16 columns, 8 warps = 8 contiguous k-splits. Thread: 8 cols x 2 batches.
// Warp smem region: ring of 4 stages x (w 8x16 | h 8x32) = 384 floats.

// ROLE 0 = layer0 (K=1152: 128 x + 1024 h), ROLE 1 = layer1 (K=2048), ROLE 2 = head (K=1024)
template <int ROLE>
__device__ __forceinline__ void produce(int s, int t, int colbase, int base_k,
                                        uint32_t warp_sm,
                                        const float* __restrict__ hA,
                                        const float* __restrict__ hB) {
    const int lane = threadIdx.x & 31;
    const int kg = base_k + s * 8;
    const float* wsrc;
    const float* hsrc;
    constexpr int WS = (ROLE == 2) ? OO : GG;
    if (ROLE == 0) {
        if (kg < II) { wsrc = Wp_ih0 + (size_t)kg * GG; hsrc = xTg + ((size_t)t * II + kg) * BB; }
        else         { wsrc = Wp_hh0 + (size_t)(kg - II) * GG; hsrc = hA + (size_t)(kg - II) * BB; }
    } else if (ROLE == 1) {
        if (kg < HH) { wsrc = Wp_ih1 + (size_t)kg * GG; hsrc = hA + (size_t)kg * BB; }
        else         { wsrc = Wp_hh1 + (size_t)(kg - HH) * GG; hsrc = hB + (size_t)(kg - HH) * BB; }
    } else {
        wsrc = Wp_out + (size_t)kg * OO; hsrc = hB + (size_t)kg * BB;
    }
    wsrc += colbase;

    const uint32_t wd = warp_sm + (unsigned)((s & 3) * STG) * 4u;
    const uint32_t hd = wd + 512u;   // after 128 w floats
    // w: 8 rows x 16 floats = 32 chunks, 1/lane
    {
        int row = lane >> 2, part = lane & 3;
        cpa16(wd + (unsigned)(row * 16 + part * 4) * 4u, wsrc + (size_t)row * WS + part * 4);
    }
    // h: 8 rows x 32 floats = 64 chunks, 2/lane
#pragma unroll
    for (int i = 0; i < 2; ++i) {
        int u = lane + i * 32;
        int row = u >> 3, part = u & 7;
        cpa16(hd + (unsigned)(row * 32 + part * 4) * 4u, hsrc + (size_t)row * BB + part * 4);
    }
}

template <int ROLE, int NS>
__device__ __forceinline__ void do_pass(int p, int t, int colbase, float* smemf, uint32_t smem_b,
                                        const float* __restrict__ b_out,
                                        float* __restrict__ out,
                                        float* creg) {
    const int tid = threadIdx.x;
    const int ks = tid >> 5;          // warp = contiguous k-split (8)
    const int lane = tid & 31;
    const int ng = lane & 1;          // 2 col-groups of 8
    const int bg = lane >> 1;         // 16 batch-pairs
    const int n0 = colbase + ng * 8;
    const int b0 = bg * 2;
    const int par = p & 1, prev = par ^ 1;
    const int base_k = ks * NS * 8;

    const float* __restrict__ hA = &h0s[prev][0][0];
    const float* __restrict__ hB = &h2s[prev][0][0];

    const uint32_t warp_sm = smem_b + (unsigned)(ks * WREG) * 4u;
    const float* warp_f = smemf + ks * WREG;

    unsigned long long acc[4][2];
#pragma unroll
    for (int i = 0; i < 4; ++i) { acc[i][0] = 0ull; acc[i][1] = 0ull; }

    // prologue: 3 stages in flight (4-buffer ring)
    produce<ROLE>(0, t, colbase, base_k, warp_sm, hA, hB); CP_COMMIT();
    produce<ROLE>(1, t, colbase, base_k, warp_sm, hA, hB); CP_COMMIT();
    produce<ROLE>(2, t, colbase, base_k, warp_sm, hA, hB); CP_COMMIT();

    for (int s = 0; s < NS; ++s) {
        if (s + 3 < NS) {
            produce<ROLE>(s + 3, t, colbase, base_k, warp_sm, hA, hB);
            CP_COMMIT();
            asm volatile("cp.async.wait_group 3;");
        } else {
            int rem = NS - 1 - s;
            if (rem == 2)      asm volatile("cp.async.wait_group 2;");
            else if (rem == 1) asm volatile("cp.async.wait_group 1;");
            else               asm volatile("cp.async.wait_group 0;");
        }
        __syncwarp();

        const float* wp = warp_f + (s & 3) * STG + ng * 8;
        const float* hp = warp_f + (s & 3) * STG + 128 + bg * 2;
#pragma unroll
        for (int r = 0; r < 8; ++r) {
            ulonglong2 w0 = *reinterpret_cast<const ulonglong2*>(wp);
            ulonglong2 w1 = *reinterpret_cast<const ulonglong2*>(wp + 4);
            uint2 hv = *reinterpret_cast<const uint2*>(hp);
            unsigned long long hd0, hd1;
            PACK2(hd0, hv.x); PACK2(hd1, hv.y);
            FMA2(acc[0][0], w0.x, hd0); FMA2(acc[0][1], w0.x, hd1);
            FMA2(acc[1][0], w0.y, hd0); FMA2(acc[1][1], w0.y, hd1);
            FMA2(acc[2][0], w1.x, hd0); FMA2(acc[2][1], w1.x, hd1);
            FMA2(acc[3][0], w1.y, hd0); FMA2(acc[3][1], w1.y, hd1);
            wp += 16;
            hp += 32;
        }
    }

    // ---- k-split reduction through smem (overlay; stage ring fully drained) ----
    __syncthreads();
    unsigned long long* red = reinterpret_cast<unsigned long long*>(smemf);
    unsigned long long* myrow = red + (size_t)tid * RPAD;
#pragma unroll
    for (int q = 0; q < 4; ++q) {
        myrow[q * 2 + 0] = acc[q][0];
        myrow[q * 2 + 1] = acc[q][1];
    }
    __syncthreads();
    if (ks == 0) {
        unsigned long long s8[8];
#pragma unroll
        for (int q = 0; q < 8; ++q) s8[q] = 0ull;
#pragma unroll
        for (int w = 0; w < 8; ++w) {
            const unsigned long long* rp = red + (size_t)(w * 32 + lane) * RPAD;
#pragma unroll
            for (int m = 0; m < 8; ++m) ADD2(s8[m], rp[m]);
        }
        // s8[q*2+b]: col-pair q of {(i,f)j0,(g,o)j0,(i,f)j1,(g,o)j1}, batch b0+b

        if (ROLE < 2) {
            const float* gbv = (ROLE == 0) ? gb0 : gb1;
            float* hdst = (ROLE == 0) ? &h0s[par][0][0] : &h2s[par][0][0];
            const int j0 = n0 >> 2;
#pragma unroll
            for (int jj = 0; jj < 2; ++jj) {
                float bi_ = gbv[n0 + jj * 4 + 0];
                float bf_ = gbv[n0 + jj * 4 + 1];
                float bg_ = gbv[n0 + jj * 4 + 2];
                float bo_ = gbv[n0 + jj * 4 + 3];
                float hv2[2];
#pragma unroll
                for (int bi = 0; bi < 2; ++bi) {
                    float2 gif = u2f(s8[(2 * jj) * 2 + bi]);      // (i, f)
                    float2 ggo = u2f(s8[(2 * jj + 1) * 2 + bi]);  // (g, o)
                    float ig = sigf(gif.x + bi_);
                    float fg = sigf(gif.y + bf_);
                    float gt = tanhfast(ggo.x + bg_);
                    float og = sigf(ggo.y + bo_);
                    float cn = fg * creg[jj * 2 + bi] + ig * gt;
                    creg[jj * 2 + bi] = cn;
                    hv2[bi] = og * tanhfast(cn);
                }
                __stcg(reinterpret_cast<float2*>(&hdst[(size_t)(j0 + jj) * BB + b0]),
                       make_float2(hv2[0], hv2[1]));
            }
        } else {
            float bo[8];
#pragma unroll
            for (int q = 0; q < 8; ++q) bo[q] = b_out[n0 + q];
#pragma unroll
            for (int bi = 0; bi < 2; ++bi) {
                float2 p0 = u2f(s8[0 + bi]);
                float2 p1 = u2f(s8[2 + bi]);
                float2 p2 = u2f(s8[4 + bi]);
                float2 p3 = u2f(s8[6 + bi]);
                float4 lo = make_float4(p0.x + bo[0], p0.y + bo[1], p1.x + bo[2], p1.y + bo[3]);
                float4 hi = make_float4(p2.x + bo[4], p2.y + bo[5], p3.x + bo[6], p3.y + bo[7]);
                float* op = out + ((size_t)(b0 + bi) * TT + t) * OO + n0;
                *reinterpret_cast<float4*>(op) = lo;
                *reinterpret_cast<float4*>(op + 4) = hi;
            }
        }
    }
}

// ---------------- persistent pipelined kernel ----------------
extern __shared__ float smemf[];

__global__ void __launch_bounds__(NTH, 4) lstm_kernel(const float* __restrict__ b_out,
                                                      float* __restrict__ out) {
    const int bid = blockIdx.x;
    const uint32_t smem_b = (uint32_t)__cvta_generic_to_shared(smemf);
    float creg[4];
#pragma unroll
    for (int i = 0; i < 4; ++i) creg[i] = 0.f;

    if (bid < 256) {
        // layer 0: t = p; K=1152, 18 stages/warp; 16 cols
        const int colbase = bid * 16;
        for (int p = 0; p < TT + 2; ++p) {
            if (p < TT) do_pass<0, 18>(p, p, colbase, smemf, smem_b, b_out, out, creg);
            grid_bar(p);
        }
    } else if (bid < 512) {
        // layer 1: t = p - 1; K=2048, 32 stages/warp
        const int colbase = (bid - 256) * 16;
        for (int p = 0; p < TT + 2; ++p) {
            if (p >= 1 && p <= TT) do_pass<1, 32>(p, p - 1, colbase, smemf, smem_b, b_out, out, creg);
            grid_bar(p);
        }
    } else {
        // head: t = p - 2; K=1024, 16 stages/warp
        const int colbase = (bid - 512) * 16;
        for (int p = 0; p < TT + 2; ++p) {
            if (p >= 2) do_pass<2, 16>(p, p - 2, colbase, smemf, smem_b, b_out, out, creg);
            grid_bar(p);
        }
    }
}

// ---------------- launch ----------------
extern "C" void kernel_launch(void* const* d_in, const int* in_sizes, int n_in,
                              void* d_out, int out_size) {
    const float* x     = (const float*)d_in[0];
    const float* Wih0  = (const float*)d_in[1];
    const float* Whh0  = (const float*)d_in[2];
    const float* b0v   = (const float*)d_in[3];
    const float* Wih1  = (const float*)d_in[4];
    const float* Whh1  = (const float*)d_in[5];
    const float* b1v   = (const float*)d_in[6];
    const float* Wout  = (const float*)d_in[7];
    const float* boutv = (const float*)d_in[8];
    float* out = (float*)d_out;

    static bool attr_set = false;
    if (!attr_set) {
        cudaFuncSetAttribute(lstm_kernel, cudaFuncAttributeMaxDynamicSharedMemorySize, SMEM_BYTES);
        attr_set = true;
    }

    prep_kernel<<<512, 256>>>(x, Wih0, Whh0, b0v, Wih1, Whh1, b1v, Wout);
    lstm_kernel<<<NBLK, NTH, SMEM_BYTES>>>(boutv, out);
}

// round 14
// speedup vs baseline: 1.5170x; 1.4812x over previous
#include <cuda_runtime.h>
#include <cuda_bf16.h>
#include <cstdint>

#define BB 32
#define TT 512
#define II 128
#define HH 1024
#define GG 4096
#define OO 128

#define NTH 256
#define NBLK 132

#define RSB 272             // padded row stride (bytes) for 128-bf16 rows
#define STAGE_BYTES 34816   // Ahi 8704 | Alo 8704 | Bhi 8704 | Blo 8704
#define OFF_ALO 8704
#define OFF_BHI 17408
#define OFF_BLO 26112
#define RING 4
#define DEX_OFF 139264      // bytes; Dex4: 4 x (32x33) f32 = 16896B
#define SMEM_BYTES 156160

// ---------------- device scratch ----------------
__device__ __nv_bfloat16 Wih0hi[GG * II], Wih0lo[GG * II];   // [n][k], n = j*4+g
__device__ __nv_bfloat16 Whh0hi[GG * HH], Whh0lo[GG * HH];
__device__ __nv_bfloat16 Wih1hi[GG * HH], Wih1lo[GG * HH];
__device__ __nv_bfloat16 Whh1hi[GG * HH], Whh1lo[GG * HH];
__device__ __nv_bfloat16 Wohi[OO * HH],  Wolo[OO * HH];      // [o][k]
__device__ float gbp0[GG], gbp1[GG];
__device__ __nv_bfloat16 xhi[TT * BB * II], xlo[TT * BB * II];  // [t][b][k]
__device__ __nv_bfloat16 h0hi[2][BB * HH], h0lo[2][BB * HH];    // [b][j]
__device__ __nv_bfloat16 h2hi[2][BB * HH], h2lo[2][BB * HH];
__device__ unsigned g_cnt, g_flag;

// ---------------- prep ----------------
__device__ __forceinline__ void split2(float v, __nv_bfloat16* hi, __nv_bfloat16* lo) {
    __nv_bfloat16 h = __float2bfloat16(v);
    *hi = h;
    *lo = __float2bfloat16(v - __bfloat162float(h));
}

__global__ void prep_kernel(const float* __restrict__ xin,
                            const float* __restrict__ Wih0, const float* __restrict__ Whh0,
                            const float* __restrict__ b0v, const float* __restrict__ Wih1,
                            const float* __restrict__ Whh1, const float* __restrict__ b1v,
                            const float* __restrict__ Wout) {
    int idx0 = blockIdx.x * blockDim.x + threadIdx.x;
    int stride = gridDim.x * blockDim.x;
    if (idx0 == 0) { g_cnt = 0u; g_flag = 0u; }

    const __nv_bfloat16 z = __float2bfloat16(0.f);
    for (int i = idx0; i < 2 * BB * HH; i += stride) {
        ((__nv_bfloat16*)h0hi)[i] = z;
        ((__nv_bfloat16*)h0lo)[i] = z;
        ((__nv_bfloat16*)h2hi)[i] = z;
        ((__nv_bfloat16*)h2lo)[i] = z;
    }

    const int SW0 = GG * II;
    const int SW1 = GG * HH;
    const int SWO = OO * HH;
    const int SXX = TT * BB * II;
    const int total = SW0 + 3 * SW1 + SWO + SXX + 2 * GG;
    for (int idx = idx0; idx < total; idx += stride) {
        int r = idx;
        if (r < SW0) {
            int n = r >> 7, k = r & (II - 1);
            int j = n >> 2, g = n & 3;
            split2(Wih0[(g * HH + j) * II + k], &Wih0hi[r], &Wih0lo[r]);
        } else if ((r -= SW0) < SW1) {
            int n = r >> 10, k = r & (HH - 1);
            int j = n >> 2, g = n & 3;
            split2(Whh0[(size_t)(g * HH + j) * HH + k], &Whh0hi[r], &Whh0lo[r]);
        } else if ((r -= SW1) < SW1) {
            int n = r >> 10, k = r & (HH - 1);
            int j = n >> 2, g = n & 3;
            split2(Wih1[(size_t)(g * HH + j) * HH + k], &Wih1hi[r], &Wih1lo[r]);
        } else if ((r -= SW1) < SW1) {
            int n = r >> 10, k = r & (HH - 1);
            int j = n >> 2, g = n & 3;
            split2(Whh1[(size_t)(g * HH + j) * HH + k], &Whh1hi[r], &Whh1lo[r]);
        } else if ((r -= SW1) < SWO) {
            split2(Wout[r], &Wohi[r], &Wolo[r]);   // [o][k] natural
        } else if ((r -= SWO) < SXX) {
            int k = r & (II - 1), b = (r >> 7) & (BB - 1), t = r >> 12;
            split2(xin[((size_t)b * TT + t) * II + k], &xhi[r], &xlo[r]);
        } else if ((r -= SXX) < GG) {
            gbp0[r] = b0v[(r & 3) * HH + (r >> 2)];
        } else {
            r -= GG;
            gbp1[r] = b1v[(r & 3) * HH + (r >> 2)];
        }
    }
}

// ---------------- helpers ----------------
__device__ __forceinline__ void cpa16(uint32_t dst, const void* src) {
    asm volatile("cp.async.cg.shared.global [%0], [%1], 16;" :: "r"(dst), "l"(src));
}
#define CP_COMMIT() asm volatile("cp.async.commit_group;")

#define LDM4(r, a) \
    asm volatile("ldmatrix.sync.aligned.m8n8.x4.shared.b16 {%0,%1,%2,%3}, [%4];" \
        : "=r"((r)[0]), "=r"((r)[1]), "=r"((r)[2]), "=r"((r)[3]) : "r"(a))

#define MMA16(c, A, b0_, b1_) \
    asm volatile("mma.sync.aligned.m16n8k16.row.col.f32.bf16.bf16.f32 " \
        "{%0,%1,%2,%3},{%4,%5,%6,%7},{%8,%9},{%0,%1,%2,%3};" \
        : "+f"((c)[0]), "+f"((c)[1]), "+f"((c)[2]), "+f"((c)[3]) \
        : "r"((A)[0]), "r"((A)[1]), "r"((A)[2]), "r"((A)[3]), "r"(b0_), "r"(b1_))

__device__ __forceinline__ float sigf(float x) { return 1.0f / (1.0f + __expf(-x)); }
__device__ __forceinline__ float tanhfast(float x) {
    return 1.0f - __fdividef(2.0f, __expf(2.0f * x) + 1.0f);
}

// ---------------- grid barrier (sense/epoch) ----------------
__device__ __forceinline__ void grid_bar(int p) {
    __threadfence();
    __syncthreads();
    if (threadIdx.x == 0) {
        unsigned tgt = (unsigned)(p + 1);
        unsigned old = atomicAdd(&g_cnt, 1u);
        if (old == tgt * NBLK - 1u) {
            asm volatile("st.global.release.gpu.u32 [%0], %1;" :: "l"(&g_flag), "r"(tgt) : "memory");
        } else {
            unsigned v;
            do {
                asm volatile("ld.global.acquire.gpu.u32 %0, [%1];" : "=r"(v) : "l"(&g_flag) : "memory");
                if (v >= tgt) break;
                __nanosleep(64);
            } while (true);
        }
    }
    __syncthreads();
}

// ---------------- stage producer ----------------
// ROLE 0: L0 K=1152 (stage0 = x/Wih0, 1..8 = h0/Whh0); ROLE 1: L1 K=2048; ROLE 2: head K=1024
template <int ROLE>
__device__ __forceinline__ void produce(int s, int slot, int t, int tile, int prev,
                                        uint32_t smem_b) {
    const int tid = threadIdx.x;
    const __nv_bfloat16 *Ah, *Al, *Bh, *Bl;
    int sA, sB;
    if (ROLE == 0) {
        if (s == 0) {
            size_t ao = (size_t)tile * 32 * II;
            Ah = Wih0hi + ao; Al = Wih0lo + ao; sA = II;
            size_t bo = (size_t)t * BB * II;
            Bh = xhi + bo; Bl = xlo + bo; sB = II;
        } else {
            int kb = (s - 1) * 128;
            size_t ao = (size_t)tile * 32 * HH + kb;
            Ah = Whh0hi + ao; Al = Whh0lo + ao; sA = HH;
            Bh = h0hi[prev] + kb; Bl = h0lo[prev] + kb; sB = HH;
        }
    } else if (ROLE == 1) {
        if (s < 8) {
            int kb = s * 128;
            size_t ao = (size_t)tile * 32 * HH + kb;
            Ah = Wih1hi + ao; Al = Wih1lo + ao; sA = HH;
            Bh = h0hi[prev] + kb; Bl = h0lo[prev] + kb; sB = HH;
        } else {
            int kb = (s - 8) * 128;
            size_t ao = (size_t)tile * 32 * HH + kb;
            Ah = Whh1hi + ao; Al = Whh1lo + ao; sA = HH;
            Bh = h2hi[prev] + kb; Bl = h2lo[prev] + kb; sB = HH;
        }
    } else {
        int kb = s * 128;
        size_t ao = (size_t)tile * 32 * HH + kb;
        Ah = Wohi + ao; Al = Wolo + ao; sA = HH;
        Bh = h2hi[prev] + kb; Bl = h2lo[prev] + kb; sB = HH;
    }
    const uint32_t base = smem_b + (unsigned)slot * STAGE_BYTES;
#pragma unroll
    for (int i = 0; i < 2; ++i) {
        int id = tid + i * NTH;
        int row = id >> 4, part = id & 15;
        uint32_t doff = (unsigned)(row * RSB + part * 16);
        cpa16(base + doff,            Ah + (size_t)row * sA + part * 8);
        cpa16(base + OFF_ALO + doff,  Al + (size_t)row * sA + part * 8);
        cpa16(base + OFF_BHI + doff,  Bh + (size_t)row * sB + part * 8);
        cpa16(base + OFF_BLO + doff,  Bl + (size_t)row * sB + part * 8);
    }
}

// ---------------- one phase: D[32 gates x 32 batch] = W . inp^T, then epilogue ----
template <int ROLE, int NS>
__device__ __forceinline__ void phase(int p, int t, int tile, uint32_t smem_b, float* smemf,
                                      const float* __restrict__ b_out,
                                      float* __restrict__ out,
                                      float* cstp, unsigned& rs) {
    const int tid = threadIdx.x;
    const int lane = tid & 31, wid = tid >> 5;
    const int mt = wid & 1;     // m16 tile (rows mt*16..)
    const int kq = wid >> 1;    // k-quarter (j16 pairs kq*2, kq*2+1)
    const int par = p & 1, prev = par ^ 1;

    float C[4][4];
#pragma unroll
    for (int n = 0; n < 4; ++n)
#pragma unroll
        for (int q = 0; q < 4; ++q) C[n][q] = 0.f;

    produce<ROLE>(0, rs & 3, t, tile, prev, smem_b); CP_COMMIT();
    produce<ROLE>(1, (rs + 1) & 3, t, tile, prev, smem_b); CP_COMMIT();

    for (int s = 0; s < NS; ++s) {
        if (s + 2 < NS) {
            produce<ROLE>(s + 2, (rs + s + 2) & 3, t, tile, prev, smem_b);
            CP_COMMIT();
            asm volatile("cp.async.wait_group 2;");
        } else if (s + 1 < NS) {
            asm volatile("cp.async.wait_group 1;");
        } else {
            asm volatile("cp.async.wait_group 0;");
        }
        __syncthreads();

        const uint32_t slot = smem_b + (unsigned)((rs + s) & 3) * STAGE_BYTES;
        // A addr: rows mt*16 + (lane&15); half-k sel (lane>>4)*16; k-window kq*64
        uint32_t aH = slot + (unsigned)((mt * 16 + (lane & 15)) * RSB + (lane >> 4) * 16 + kq * 64);
        uint32_t aL = aH + OFF_ALO;
        // B addr (x4 covers 2 n8 tiles): row = g*16 + (lane&7) + (lane>>4)*8; koff (lane>>3 &1)*16
        const uint32_t brow = (unsigned)(((lane & 7) + ((lane >> 4) << 3)) * RSB +
                                         ((lane >> 3) & 1) * 16 + kq * 64);
        uint32_t b0H = slot + OFF_BHI + brow;
        uint32_t b1H = b0H + 16 * RSB;
        uint32_t b0L = slot + OFF_BLO + brow;
        uint32_t b1L = b0L + 16 * RSB;

#pragma unroll
        for (int jj = 0; jj < 2; ++jj) {
            uint32_t ah[4], al[4], bh0[4], bh1[4], bl0[4], bl1[4];
            LDM4(ah, aH); LDM4(al, aL);
            LDM4(bh0, b0H); LDM4(bh1, b1H);
            LDM4(bl0, b0L); LDM4(bl1, b1L);
            // term Ah*Bh
            MMA16(C[0], ah, bh0[0], bh0[1]); MMA16(C[1], ah, bh0[2], bh0[3]);
            MMA16(C[2], ah, bh1[0], bh1[1]); MMA16(C[3], ah, bh1[2], bh1[3]);
            // term Ah*Bl
            MMA16(C[0], ah, bl0[0], bl0[1]); MMA16(C[1], ah, bl0[2], bl0[3]);
            MMA16(C[2], ah, bl1[0], bl1[1]); MMA16(C[3], ah, bl1[2], bl1[3]);
            // term Al*Bh
            MMA16(C[0], al, bh0[0], bh0[1]); MMA16(C[1], al, bh0[2], bh0[3]);
            MMA16(C[2], al, bh1[0], bh1[1]); MMA16(C[3], al, bh1[2], bh1[3]);
            aH += 32; aL += 32; b0H += 32; b1H += 32; b0L += 32; b1L += 32;
        }
    }
    rs += NS;

    // ---- dump C to Dex4[kq] (33-float row stride) ----
    float* Dex = smemf + DEX_OFF / 4 + kq * (32 * 33);
    const int r0 = mt * 16 + (lane >> 2);
    const int c0 = (lane & 3) * 2;
#pragma unroll
    for (int n = 0; n < 4; ++n) {
        Dex[r0 * 33 + n * 8 + c0]           = C[n][0];
        Dex[r0 * 33 + n * 8 + c0 + 1]       = C[n][1];
        Dex[(r0 + 8) * 33 + n * 8 + c0]     = C[n][2];
        Dex[(r0 + 8) * 33 + n * 8 + c0 + 1] = C[n][3];
    }
    __syncthreads();

    float* D0 = smemf + DEX_OFF / 4;
    if (ROLE < 2) {
        const int jl = tid >> 5;     // hidden unit (local 0..7)
        const int b = lane;          // batch
        float sg[4];
#pragma unroll
        for (int g = 0; g < 4; ++g) {
            int ro = (4 * jl + g) * 33 + b;
            sg[g] = D0[ro] + D0[ro + 1056] + D0[ro + 2112] + D0[ro + 3168];
        }
        const float* gbv = (ROLE == 0) ? gbp0 : gbp1;
        const int nb = tile * 32 + 4 * jl;
        float ig = sigf(sg[0] + gbv[nb]);
        float fg = sigf(sg[1] + gbv[nb + 1]);
        float gt = tanhfast(sg[2] + gbv[nb + 2]);
        float og = sigf(sg[3] + gbv[nb + 3]);
        float cn = fg * (*cstp) + ig * gt;
        *cstp = cn;
        float h = og * tanhfast(cn);
        __nv_bfloat16 hh = __float2bfloat16(h);
        __nv_bfloat16 hl = __float2bfloat16(h - __bfloat162float(hh));
        const int jg = tile * 8 + jl;
        __nv_bfloat16* dh = (ROLE == 0) ? h0hi[par] : h2hi[par];
        __nv_bfloat16* dl = (ROLE == 0) ? h0lo[par] : h2lo[par];
        dh[(size_t)b * HH + jg] = hh;
        dl[(size_t)b * HH + jg] = hl;
    } else {
        const int b = lane;
#pragma unroll
        for (int q = 0; q < 4; ++q) {
            int o = (tid >> 5) + q * 8;
            int ro = o * 33 + b;
            float v = D0[ro] + D0[ro + 1056] + D0[ro + 2112] + D0[ro + 3168];
            int og = tile * 32 + o;
            out[((size_t)b * TT + t) * OO + og] = v + b_out[og];
        }
    }
    __syncthreads();
}

// ---------------- persistent kernel ----------------
extern __shared__ float smemf[];

__global__ void __launch_bounds__(NTH, 1)
lstm_kernel(const float* __restrict__ b_out, float* __restrict__ out) {
    const int bid = blockIdx.x;
    const uint32_t smem_b = (uint32_t)__cvta_generic_to_shared(smemf);
    float cst[2] = {0.f, 0.f};
    unsigned rs = 0;

    if (bid < 128) {
        // combined: L0 tile bid at t=p, then L1 tile bid at t=p-1
        for (int p = 0; p < TT + 2; ++p) {
            if (p < TT)
                phase<0, 9>(p, p, bid, smem_b, smemf, b_out, out, &cst[0], rs);
            if (p >= 1 && p <= TT)
                phase<1, 16>(p, p - 1, bid, smem_b, smemf, b_out, out, &cst[1], rs);
            grid_bar(p);
        }
    } else {
        const int tile = bid - 128;   // head tiles 0..3 (32 out-rows each)
        for (int p = 0; p < TT + 2; ++p) {
            if (p >= 2)
                phase<2, 8>(p, p - 2, tile, smem_b, smemf, b_out, out, &cst[0], rs);
            grid_bar(p);
        }
    }
}

// ---------------- launch ----------------
extern "C" void kernel_launch(void* const* d_in, const int* in_sizes, int n_in,
                              void* d_out, int out_size) {
    const float* x     = (const float*)d_in[0];
    const float* Wih0  = (const float*)d_in[1];
    const float* Whh0  = (const float*)d_in[2];
    const float* b0v   = (const float*)d_in[3];
    const float* Wih1  = (const float*)d_in[4];
    const float* Whh1  = (const float*)d_in[5];
    const float* b1v   = (const float*)d_in[6];
    const float* Wout  = (const float*)d_in[7];
    const float* boutv = (const float*)d_in[8];
    float* out = (float*)d_out;

    // Must NOT run during graph capture (capture-poisoning API call):
    // first harness call is uncaptured -> set once, replays skip.
    static bool attr_set = false;
    if (!attr_set) {
        cudaFuncSetAttribute(lstm_kernel, cudaFuncAttributeMaxDynamicSharedMemorySize, SMEM_BYTES);
        attr_set = true;
    }

    prep_kernel<<<512, 256>>>(x, Wih0, Whh0, b0v, Wih1, Whh1, b1v, Wout);
    lstm_kernel<<<NBLK, NTH, SMEM_BYTES>>>(boutv, out);
}

// round 15
// speedup vs baseline: 1.5907x; 1.0486x over previous
#include <cuda_runtime.h>
#include <cuda_bf16.h>
#include <cstdint>

#define BB 32
#define TT 512
#define II 128
#define HH 1024
#define GG 4096
#define OO 128

#define NTH 512
#define NBLK 132

#define RSB 272             // padded row stride (bytes) for 128-bf16 rows
#define STAGE_BYTES 34816   // Ahi 8704 | Alo 8704 | Bhi 8704 | Blo 8704
#define OFF_ALO 8704
#define OFF_BHI 17408
#define OFF_BLO 26112
#define RING 4
#define DEX_OFF 139264      // bytes; Dex8: 8 x (32x33) f32 = 33792B
#define SMEM_BYTES 173056

// ---------------- device scratch ----------------
__device__ __nv_bfloat16 Wih0hi[GG * II], Wih0lo[GG * II];   // [n][k], n = j*4+g
__device__ __nv_bfloat16 Whh0hi[GG * HH], Whh0lo[GG * HH];
__device__ __nv_bfloat16 Wih1hi[GG * HH], Wih1lo[GG * HH];
__device__ __nv_bfloat16 Whh1hi[GG * HH], Whh1lo[GG * HH];
__device__ __nv_bfloat16 Wohi[OO * HH],  Wolo[OO * HH];      // [o][k]
__device__ float gbp0[GG], gbp1[GG];
__device__ __nv_bfloat16 xhi[TT * BB * II], xlo[TT * BB * II];  // [t][b][k]
__device__ __nv_bfloat16 h0hi[2][BB * HH], h0lo[2][BB * HH];    // [b][j]
__device__ __nv_bfloat16 h2hi[2][BB * HH], h2lo[2][BB * HH];
__device__ unsigned g_cnt, g_flag;

// ---------------- prep ----------------
__device__ __forceinline__ void split2(float v, __nv_bfloat16* hi, __nv_bfloat16* lo) {
    __nv_bfloat16 h = __float2bfloat16(v);
    *hi = h;
    *lo = __float2bfloat16(v - __bfloat162float(h));
}

__global__ void prep_kernel(const float* __restrict__ xin,
                            const float* __restrict__ Wih0, const float* __restrict__ Whh0,
                            const float* __restrict__ b0v, const float* __restrict__ Wih1,
                            const float* __restrict__ Whh1, const float* __restrict__ b1v,
                            const float* __restrict__ Wout) {
    int idx0 = blockIdx.x * blockDim.x + threadIdx.x;
    int stride = gridDim.x * blockDim.x;
    if (idx0 == 0) { g_cnt = 0u; g_flag = 0u; }

    const __nv_bfloat16 z = __float2bfloat16(0.f);
    for (int i = idx0; i < 2 * BB * HH; i += stride) {
        ((__nv_bfloat16*)h0hi)[i] = z;
        ((__nv_bfloat16*)h0lo)[i] = z;
        ((__nv_bfloat16*)h2hi)[i] = z;
        ((__nv_bfloat16*)h2lo)[i] = z;
    }

    const int SW0 = GG * II;
    const int SW1 = GG * HH;
    const int SWO = OO * HH;
    const int SXX = TT * BB * II;
    const int total = SW0 + 3 * SW1 + SWO + SXX + 2 * GG;
    for (int idx = idx0; idx < total; idx += stride) {
        int r = idx;
        if (r < SW0) {
            int n = r >> 7, k = r & (II - 1);
            int j = n >> 2, g = n & 3;
            split2(Wih0[(g * HH + j) * II + k], &Wih0hi[r], &Wih0lo[r]);
        } else if ((r -= SW0) < SW1) {
            int n = r >> 10, k = r & (HH - 1);
            int j = n >> 2, g = n & 3;
            split2(Whh0[(size_t)(g * HH + j) * HH + k], &Whh0hi[r], &Whh0lo[r]);
        } else if ((r -= SW1) < SW1) {
            int n = r >> 10, k = r & (HH - 1);
            int j = n >> 2, g = n & 3;
            split2(Wih1[(size_t)(g * HH + j) * HH + k], &Wih1hi[r], &Wih1lo[r]);
        } else if ((r -= SW1) < SW1) {
            int n = r >> 10, k = r & (HH - 1);
            int j = n >> 2, g = n & 3;
            split2(Whh1[(size_t)(g * HH + j) * HH + k], &Whh1hi[r], &Whh1lo[r]);
        } else if ((r -= SW1) < SWO) {
            split2(Wout[r], &Wohi[r], &Wolo[r]);   // [o][k] natural
        } else if ((r -= SWO) < SXX) {
            int k = r & (II - 1), b = (r >> 7) & (BB - 1), t = r >> 12;
            split2(xin[((size_t)b * TT + t) * II + k], &xhi[r], &xlo[r]);
        } else if ((r -= SXX) < GG) {
            gbp0[r] = b0v[(r & 3) * HH + (r >> 2)];
        } else {
            r -= GG;
            gbp1[r] = b1v[(r & 3) * HH + (r >> 2)];
        }
    }
}

// ---------------- helpers ----------------
__device__ __forceinline__ void cpa16(uint32_t dst, const void* src) {
    asm volatile("cp.async.cg.shared.global [%0], [%1], 16;" :: "r"(dst), "l"(src));
}
#define CP_COMMIT() asm volatile("cp.async.commit_group;")

#define LDM4(r, a) \
    asm volatile("ldmatrix.sync.aligned.m8n8.x4.shared.b16 {%0,%1,%2,%3}, [%4];" \
        : "=r"((r)[0]), "=r"((r)[1]), "=r"((r)[2]), "=r"((r)[3]) : "r"(a))

#define MMA16(c, A, b0_, b1_) \
    asm volatile("mma.sync.aligned.m16n8k16.row.col.f32.bf16.bf16.f32 " \
        "{%0,%1,%2,%3},{%4,%5,%6,%7},{%8,%9},{%0,%1,%2,%3};" \
        : "+f"((c)[0]), "+f"((c)[1]), "+f"((c)[2]), "+f"((c)[3]) \
        : "r"((A)[0]), "r"((A)[1]), "r"((A)[2]), "r"((A)[3]), "r"(b0_), "r"(b1_))

__device__ __forceinline__ float sigf(float x) { return 1.0f / (1.0f + __expf(-x)); }
__device__ __forceinline__ float tanhfast(float x) {
    return 1.0f - __fdividef(2.0f, __expf(2.0f * x) + 1.0f);
}

// ---------------- grid barrier (sense/epoch) ----------------
__device__ __forceinline__ void grid_bar(int p) {
    if (threadIdx.x < 256) __threadfence();   // h/out writers are warps 0-7
    __syncthreads();
    if (threadIdx.x == 0) {
        unsigned tgt = (unsigned)(p + 1);
        unsigned old = atomicAdd(&g_cnt, 1u);
        if (old == tgt * NBLK - 1u) {
            asm volatile("st.global.release.gpu.u32 [%0], %1;" :: "l"(&g_flag), "r"(tgt) : "memory");
        } else {
            unsigned v;
            do {
                asm volatile("ld.global.acquire.gpu.u32 %0, [%1];" : "=r"(v) : "l"(&g_flag) : "memory");
                if (v >= tgt) break;
                __nanosleep(64);
            } while (true);
        }
    }
    __syncthreads();
}

// ---------------- stage producer ----------------
// ROLE 0: L0 K=1152 (stage0 = x/Wih0, 1..8 = h0/Whh0); ROLE 1: L1 K=2048; ROLE 2: head K=1024
template <int ROLE>
__device__ __forceinline__ void produce(int s, int slot, int t, int tile, int prev,
                                        uint32_t smem_b) {
    const int tid = threadIdx.x;
    const __nv_bfloat16 *Ah, *Al, *Bh, *Bl;
    int sA, sB;
    if (ROLE == 0) {
        if (s == 0) {
            size_t ao = (size_t)tile * 32 * II;
            Ah = Wih0hi + ao; Al = Wih0lo + ao; sA = II;
            size_t bo = (size_t)t * BB * II;
            Bh = xhi + bo; Bl = xlo + bo; sB = II;
        } else {
            int kb = (s - 1) * 128;
            size_t ao = (size_t)tile * 32 * HH + kb;
            Ah = Whh0hi + ao; Al = Whh0lo + ao; sA = HH;
            Bh = h0hi[prev] + kb; Bl = h0lo[prev] + kb; sB = HH;
        }
    } else if (ROLE == 1) {
        if (s < 8) {
            int kb = s * 128;
            size_t ao = (size_t)tile * 32 * HH + kb;
            Ah = Wih1hi + ao; Al = Wih1lo + ao; sA = HH;
            Bh = h0hi[prev] + kb; Bl = h0lo[prev] + kb; sB = HH;
        } else {
            int kb = (s - 8) * 128;
            size_t ao = (size_t)tile * 32 * HH + kb;
            Ah = Whh1hi + ao; Al = Whh1lo + ao; sA = HH;
            Bh = h2hi[prev] + kb; Bl = h2lo[prev] + kb; sB = HH;
        }
    } else {
        int kb = s * 128;
        size_t ao = (size_t)tile * 32 * HH + kb;
        Ah = Wohi + ao; Al = Wolo + ao; sA = HH;
        Bh = h2hi[prev] + kb; Bl = h2lo[prev] + kb; sB = HH;
    }
    const uint32_t base = smem_b + (unsigned)slot * STAGE_BYTES;
    {
        int row = tid >> 4, part = tid & 15;
        uint32_t doff = (unsigned)(row * RSB + part * 16);
        cpa16(base + doff,            Ah + (size_t)row * sA + part * 8);
        cpa16(base + OFF_ALO + doff,  Al + (size_t)row * sA + part * 8);
        cpa16(base + OFF_BHI + doff,  Bh + (size_t)row * sB + part * 8);
        cpa16(base + OFF_BLO + doff,  Bl + (size_t)row * sB + part * 8);
    }
}

// ---------------- one phase: D[32 gates x 32 batch] = W . inp^T, then epilogue ----
template <int ROLE, int NS>
__device__ __forceinline__ void phase(int p, int t, int tile, uint32_t smem_b, float* smemf,
                                      const float* __restrict__ b_out,
                                      float* __restrict__ out,
                                      float* cstp, unsigned& rs) {
    const int tid = threadIdx.x;
    const int lane = tid & 31, wid = tid >> 5;
    const int mt = wid & 1;     // m16 tile (rows mt*16..)
    const int kq = wid >> 1;    // k16 slice (0..7)
    const int par = p & 1, prev = par ^ 1;

    float C[4][4];
#pragma unroll
    for (int n = 0; n < 4; ++n)
#pragma unroll
        for (int q = 0; q < 4; ++q) C[n][q] = 0.f;

    produce<ROLE>(0, rs & 3, t, tile, prev, smem_b); CP_COMMIT();
    produce<ROLE>(1, (rs + 1) & 3, t, tile, prev, smem_b); CP_COMMIT();

    for (int s = 0; s < NS; ++s) {
        if (s + 2 < NS) {
            produce<ROLE>(s + 2, (rs + s + 2) & 3, t, tile, prev, smem_b);
            CP_COMMIT();
            asm volatile("cp.async.wait_group 2;");
        } else if (s + 1 < NS) {
            asm volatile("cp.async.wait_group 1;");
        } else {
            asm volatile("cp.async.wait_group 0;");
        }
        __syncthreads();

        const uint32_t slot = smem_b + (unsigned)((rs + s) & 3) * STAGE_BYTES;
        // A: rows mt*16 + (lane&15); k-halves (lane>>4)*16B; k16 window kq*32B
        uint32_t aH = slot + (unsigned)((mt * 16 + (lane & 15)) * RSB + (lane >> 4) * 16 + kq * 32);
        uint32_t aL = aH + OFF_ALO;
        // B (x4 = 2 n8-tiles x k16): rows (lane&7)+((lane>>4)<<3); k-half ((lane>>3)&1)*16B
        const uint32_t brow = (unsigned)(((lane & 7) + ((lane >> 4) << 3)) * RSB +
                                         ((lane >> 3) & 1) * 16 + kq * 32);
        uint32_t b0H = slot + OFF_BHI + brow;
        uint32_t b1H = b0H + 16 * RSB;
        uint32_t b0L = slot + OFF_BLO + brow;
        uint32_t b1L = b0L + 16 * RSB;

        uint32_t ah[4], al[4], bh0[4], bh1[4], bl0[4], bl1[4];
        LDM4(ah, aH); LDM4(al, aL);
        LDM4(bh0, b0H); LDM4(bh1, b1H);
        LDM4(bl0, b0L); LDM4(bl1, b1L);
        // term Ah*Bh
        MMA16(C[0], ah, bh0[0], bh0[1]); MMA16(C[1], ah, bh0[2], bh0[3]);
        MMA16(C[2], ah, bh1[0], bh1[1]); MMA16(C[3], ah, bh1[2], bh1[3]);
        // term Ah*Bl
        MMA16(C[0], ah, bl0[0], bl0[1]); MMA16(C[1], ah, bl0[2], bl0[3]);
        MMA16(C[2], ah, bl1[0], bl1[1]); MMA16(C[3], ah, bl1[2], bl1[3]);
        // term Al*Bh
        MMA16(C[0], al, bh0[0], bh0[1]); MMA16(C[1], al, bh0[2], bh0[3]);
        MMA16(C[2], al, bh1[0], bh1[1]); MMA16(C[3], al, bh1[2], bh1[3]);
    }
    rs += NS;

    // ---- dump C to Dex8[kq] (33-float row stride) ----
    float* Dex = smemf + DEX_OFF / 4 + kq * (32 * 33);
    const int r0 = mt * 16 + (lane >> 2);
    const int c0 = (lane & 3) * 2;
#pragma unroll
    for (int n = 0; n < 4; ++n) {
        Dex[r0 * 33 + n * 8 + c0]           = C[n][0];
        Dex[r0 * 33 + n * 8 + c0 + 1]       = C[n][1];
        Dex[(r0 + 8) * 33 + n * 8 + c0]     = C[n][2];
        Dex[(r0 + 8) * 33 + n * 8 + c0 + 1] = C[n][3];
    }
    __syncthreads();

    float* D0 = smemf + DEX_OFF / 4;
    if (ROLE < 2) {
        if (wid < 8) {
            const int jl = wid;      // hidden unit (local 0..7)
            const int b = lane;      // batch
            float sg[4];
#pragma unroll
            for (int g = 0; g < 4; ++g) {
                int ro = (4 * jl + g) * 33 + b;
                float v = 0.f;
#pragma unroll
                for (int q = 0; q < 8; ++q) v += D0[ro + q * 1056];
                sg[g] = v;
            }
            const float* gbv = (ROLE == 0) ? gbp0 : gbp1;
            const int nb = tile * 32 + 4 * jl;
            float ig = sigf(sg[0] + gbv[nb]);
            float fg = sigf(sg[1] + gbv[nb + 1]);
            float gt = tanhfast(sg[2] + gbv[nb + 2]);
            float og = sigf(sg[3] + gbv[nb + 3]);
            float cn = fg * (*cstp) + ig * gt;
            *cstp = cn;
            float h = og * tanhfast(cn);
            __nv_bfloat16 hh = __float2bfloat16(h);
            __nv_bfloat16 hl = __float2bfloat16(h - __bfloat162float(hh));
            const int jg = tile * 8 + jl;
            __nv_bfloat16* dh = (ROLE == 0) ? h0hi[par] : h2hi[par];
            __nv_bfloat16* dl = (ROLE == 0) ? h0lo[par] : h2lo[par];
            dh[(size_t)b * HH + jg] = hh;
            dl[(size_t)b * HH + jg] = hl;
        }
    } else {
        if (wid < 8) {
            const int b = lane;
#pragma unroll
            for (int q4 = 0; q4 < 4; ++q4) {
                int o = wid + q4 * 8;
                int ro = o * 33 + b;
                float v = 0.f;
#pragma unroll
                for (int q = 0; q < 8; ++q) v += D0[ro + q * 1056];
                int og = tile * 32 + o;
                out[((size_t)b * TT + t) * OO + og] = v + b_out[og];
            }
        }
    }
    __syncthreads();
}

// ---------------- persistent kernel ----------------
extern __shared__ float smemf[];

__global__ void __launch_bounds__(NTH, 1)
lstm_kernel(const float* __restrict__ b_out, float* __restrict__ out) {
    const int bid = blockIdx.x;
    const uint32_t smem_b = (uint32_t)__cvta_generic_to_shared(smemf);
    float cst[2] = {0.f, 0.f};
    unsigned rs = 0;

    if (bid < 128) {
        // combined: L0 tile bid at t=p, then L1 tile bid at t=p-1
        for (int p = 0; p < TT + 2; ++p) {
            if (p < TT)
                phase<0, 9>(p, p, bid, smem_b, smemf, b_out, out, &cst[0], rs);
            if (p >= 1 && p <= TT)
                phase<1, 16>(p, p - 1, bid, smem_b, smemf, b_out, out, &cst[1], rs);
            grid_bar(p);
        }
    } else {
        const int tile = bid - 128;   // head tiles 0..3 (32 out-rows each)
        for (int p = 0; p < TT + 2; ++p) {
            if (p >= 2)
                phase<2, 8>(p, p - 2, tile, smem_b, smemf, b_out, out, &cst[0], rs);
            grid_bar(p);
        }
    }
}

// ---------------- launch ----------------
extern "C" void kernel_launch(void* const* d_in, const int* in_sizes, int n_in,
                              void* d_out, int out_size) {
    const float* x     = (const float*)d_in[0];
    const float* Wih0  = (const float*)d_in[1];
    const float* Whh0  = (const float*)d_in[2];
    const float* b0v   = (const float*)d_in[3];
    const float* Wih1  = (const float*)d_in[4];
    const float* Whh1  = (const float*)d_in[5];
    const float* b1v   = (const float*)d_in[6];
    const float* Wout  = (const float*)d_in[7];
    const float* boutv = (const float*)d_in[8];
    float* out = (float*)d_out;

    // Must NOT run during graph capture (capture-poisoning API call):
    // first harness call is uncaptured -> set once, replays skip.
    static bool attr_set = false;
    if (!attr_set) {
        cudaFuncSetAttribute(lstm_kernel, cudaFuncAttributeMaxDynamicSharedMemorySize, SMEM_BYTES);
        attr_set = true;
    }

    prep_kernel<<<512, 256>>>(x, Wih0, Whh0, b0v, Wih1, Whh1, b1v, Wout);
    lstm_kernel<<<NBLK, NTH, SMEM_BYTES>>>(boutv, out);
}